// round 1
// baseline (speedup 1.0000x reference)
#include <cuda_runtime.h>
#include <math.h>

#define BATCH 64
#define SEQ 256
#define EMBED 512
#define HIDDEN 1024
#define GATES (4*HIDDEN)
#define MTOT (BATCH*SEQ)   // 16384

// Scratch (allocation-free rule: __device__ globals)
__device__ float g_Xg[(size_t)MTOT * GATES];     // 268 MB: x@W_ih^T + b_ih + b_hh
__device__ float g_Hout[(size_t)MTOT * HIDDEN];  // 67 MB: all h_t
__device__ float g_hA[HIDDEN * BATCH];           // h transposed [j][b]
__device__ float g_hB[HIDDEN * BATCH];
__device__ float g_cT[HIDDEN * BATCH];           // c transposed [j][b]

__global__ void zero_state_kernel() {
    int i = blockIdx.x * blockDim.x + threadIdx.x;
    if (i < HIDDEN * BATCH) { g_hA[i] = 0.0f; g_cT[i] = 0.0f; }
}

// C[M,N] = A[M,K] @ B[N,K]^T + bias1[n] (+ bias2[n])
// BM=BN=128, BK=8, 256 threads, 8x8 microtile.
__global__ __launch_bounds__(256, 2)
void sgemm_bias(const float* __restrict__ A, const float* __restrict__ Bw,
                const float* __restrict__ bias1, const float* __restrict__ bias2,
                float* __restrict__ C, int M, int N, int K)
{
    __shared__ float As[8][128];
    __shared__ float Bs[8][128];
    const int m0 = blockIdx.y * 128;
    const int n0 = blockIdx.x * 128;
    const int tid = threadIdx.x;
    const int row = tid >> 1;          // 0..127
    const int kq  = (tid & 1) * 4;     // 0 or 4
    const int tx = tid & 15;           // n micro group
    const int ty = tid >> 4;           // m micro group

    float acc[8][8];
#pragma unroll
    for (int i = 0; i < 8; i++)
#pragma unroll
        for (int j = 0; j < 8; j++) acc[i][j] = 0.0f;

    const float* Arow = A + (size_t)(m0 + row) * K + kq;
    const float* Brow = Bw + (size_t)(n0 + row) * K + kq;

    for (int k0 = 0; k0 < K; k0 += 8) {
        float4 a4 = *(const float4*)(Arow + k0);
        float4 b4 = *(const float4*)(Brow + k0);
        As[kq+0][row] = a4.x; As[kq+1][row] = a4.y; As[kq+2][row] = a4.z; As[kq+3][row] = a4.w;
        Bs[kq+0][row] = b4.x; Bs[kq+1][row] = b4.y; Bs[kq+2][row] = b4.z; Bs[kq+3][row] = b4.w;
        __syncthreads();
#pragma unroll
        for (int kk = 0; kk < 8; kk++) {
            const float4 a0 = *(const float4*)&As[kk][ty*8];
            const float4 a1 = *(const float4*)&As[kk][ty*8+4];
            const float4 b0 = *(const float4*)&Bs[kk][tx*8];
            const float4 b1 = *(const float4*)&Bs[kk][tx*8+4];
            const float ar[8] = {a0.x,a0.y,a0.z,a0.w,a1.x,a1.y,a1.z,a1.w};
            const float br[8] = {b0.x,b0.y,b0.z,b0.w,b1.x,b1.y,b1.z,b1.w};
#pragma unroll
            for (int i = 0; i < 8; i++)
#pragma unroll
                for (int j = 0; j < 8; j++) acc[i][j] += ar[i] * br[j];
        }
        __syncthreads();
    }

    float bb[8];
#pragma unroll
    for (int j = 0; j < 8; j++) {
        int n = n0 + tx*8 + j;
        float s = bias1 ? bias1[n] : 0.0f;
        if (bias2) s += bias2[n];
        bb[j] = s;
    }
#pragma unroll
    for (int i = 0; i < 8; i++) {
        int m = m0 + ty*8 + i;
        float* Crow = C + (size_t)m * N + n0 + tx*8;
#pragma unroll
        for (int j = 0; j < 8; j++) Crow[j] = acc[i][j] + bb[j];
    }
}

__device__ __forceinline__ float sigf(float x) { return 1.0f / (1.0f + expf(-x)); }

// One LSTM step. Grid: 128 blocks (j-tiles of 8 hidden units), 128 threads.
// hprev/hnext are transposed [j][b]; cT transposed [j][b].
__global__ __launch_bounds__(128)
void lstm_step(const float* __restrict__ Xg, const float* __restrict__ Whh,
               const float* __restrict__ hprev, float* __restrict__ hnext,
               float* __restrict__ cT, float* __restrict__ Hout, int t)
{
    __shared__ float sh[32*64];    // h chunk [k][b]; reused as gates [r][b]
    __shared__ float sW[32*36];    // W chunk [k][r] (pad 36)
    __shared__ float sX[64*32];    // Xg tile [b][gate*8+jj]

    const int tid = threadIdx.x;
    const int j0 = blockIdx.x * 8;

    // Prefetch Xg tile (consumed only at epilogue)
#pragma unroll
    for (int i = 0; i < 4; i++) {
        int f = i*128 + tid;                 // 0..511 float4s
        int b = f >> 3;
        int rem = f & 7;
        int gate = rem >> 1;
        int part = (rem & 1) * 4;
        float4 v = *(const float4*)(Xg + ((size_t)(b*SEQ + t))*GATES + gate*HIDDEN + j0 + part);
        *(float4*)&sX[b*32 + gate*8 + part] = v;
    }

    const int ridx = tid >> 2;              // 0..31 (gate-row within tile)
    const int kq = (tid & 3) * 8;
    const int grow = (ridx >> 3) * HIDDEN + j0 + (ridx & 7);
    const int tx = tid & 15;                // batch group (4 b)
    const int ty = tid >> 4;                // row group (4 r)
    const int r0 = ty * 4;

    float acc[4][4];
#pragma unroll
    for (int i = 0; i < 4; i++)
#pragma unroll
        for (int j = 0; j < 4; j++) acc[i][j] = 0.0f;

    const float* Wrow = Whh + (size_t)grow * HIDDEN + kq;

    for (int k0 = 0; k0 < HIDDEN; k0 += 32) {
        // h tile: layout matches global [k][b] exactly
#pragma unroll
        for (int i = 0; i < 4; i++)
            ((float4*)sh)[i*128 + tid] = ((const float4*)hprev)[k0*16 + i*128 + tid];
        // W tile -> sW[k][r]
#pragma unroll
        for (int u = 0; u < 2; u++) {
            float4 w4 = *(const float4*)(Wrow + k0 + u*4);
            sW[(kq+u*4+0)*36 + ridx] = w4.x;
            sW[(kq+u*4+1)*36 + ridx] = w4.y;
            sW[(kq+u*4+2)*36 + ridx] = w4.z;
            sW[(kq+u*4+3)*36 + ridx] = w4.w;
        }
        __syncthreads();
#pragma unroll
        for (int kk = 0; kk < 32; kk++) {
            float4 h4 = ((const float4*)sh)[kk*16 + tx];
            float4 w4 = *(const float4*)&sW[kk*36 + r0];
            const float hr[4] = {h4.x, h4.y, h4.z, h4.w};
            const float wr[4] = {w4.x, w4.y, w4.z, w4.w};
#pragma unroll
            for (int i = 0; i < 4; i++)
#pragma unroll
                for (int j = 0; j < 4; j++) acc[i][j] += wr[i] * hr[j];
        }
        __syncthreads();
    }

    // gates = acc + Xg ; stash in sh as [r (32)][b (64)]
    const int b0 = tx * 4;
#pragma unroll
    for (int i = 0; i < 4; i++) {
        int r = r0 + i;
        int gate = r >> 3;
        int jj = r & 7;
#pragma unroll
        for (int j = 0; j < 4; j++)
            sh[r*64 + b0 + j] = acc[i][j] + sX[(b0+j)*32 + gate*8 + jj];
    }
    __syncthreads();

    // Elementwise update: thread -> (jl = tid>>4, 4 consecutive b)
    const int jl = tid >> 4;            // 0..7
    const int bb = (tid & 15) * 4;      // 0..60
    float4 ig = *(const float4*)&sh[( 0 + jl)*64 + bb];
    float4 fg = *(const float4*)&sh[( 8 + jl)*64 + bb];
    float4 gg = *(const float4*)&sh[(16 + jl)*64 + bb];
    float4 og = *(const float4*)&sh[(24 + jl)*64 + bb];
    const int jglob = j0 + jl;
    float4 c4 = *(const float4*)&cT[jglob*64 + bb];

    float iv[4] = {ig.x, ig.y, ig.z, ig.w};
    float fv[4] = {fg.x, fg.y, fg.z, fg.w};
    float gv[4] = {gg.x, gg.y, gg.z, gg.w};
    float ov[4] = {og.x, og.y, og.z, og.w};
    float cv[4] = {c4.x, c4.y, c4.z, c4.w};
    float hv[4];
#pragma unroll
    for (int q = 0; q < 4; q++) {
        float cn = sigf(fv[q]) * cv[q] + sigf(iv[q]) * tanhf(gv[q]);
        cv[q] = cn;
        hv[q] = sigf(ov[q]) * tanhf(cn);
    }
    *(float4*)&cT[jglob*64 + bb]    = make_float4(cv[0], cv[1], cv[2], cv[3]);
    *(float4*)&hnext[jglob*64 + bb] = make_float4(hv[0], hv[1], hv[2], hv[3]);
#pragma unroll
    for (int q = 0; q < 4; q++)
        Hout[((size_t)(bb+q)*SEQ + t)*HIDDEN + jglob] = hv[q];
}

extern "C" void kernel_launch(void* const* d_in, const int* in_sizes, int n_in,
                              void* d_out, int out_size)
{
    const float* embedded = (const float*)d_in[0];  // [B,T,E]
    const float* W_ih     = (const float*)d_in[1];  // [4H,E]
    const float* W_hh     = (const float*)d_in[2];  // [4H,H]
    const float* b_ih     = (const float*)d_in[3];  // [4H]
    const float* b_hh     = (const float*)d_in[4];  // [4H]
    const float* W_fc     = (const float*)d_in[5];  // [H,H]
    const float* b_fc     = (const float*)d_in[6];  // [H]
    float* out = (float*)d_out;                     // [B,T,H]

    float *dXg, *dHout, *dhA, *dhB, *dcT;
    cudaGetSymbolAddress((void**)&dXg,   g_Xg);
    cudaGetSymbolAddress((void**)&dHout, g_Hout);
    cudaGetSymbolAddress((void**)&dhA,   g_hA);
    cudaGetSymbolAddress((void**)&dhB,   g_hB);
    cudaGetSymbolAddress((void**)&dcT,   g_cT);

    // 1. zero h, c
    zero_state_kernel<<<(HIDDEN*BATCH + 255)/256, 256>>>();

    // 2. Xg = embedded @ W_ih^T + b_ih + b_hh   (M=16384, N=4096, K=512)
    {
        dim3 grid(GATES/128, MTOT/128);
        sgemm_bias<<<grid, 256>>>(embedded, W_ih, b_ih, b_hh, dXg, MTOT, GATES, EMBED);
    }

    // 3. recurrence
    for (int t = 0; t < SEQ; t++) {
        const float* hr = (t & 1) ? dhB : dhA;
        float*       hw = (t & 1) ? dhA : dhB;
        lstm_step<<<HIDDEN/8, 128>>>(dXg, W_hh, hr, hw, dcT, dHout, t);
    }

    // 4. out = Hout @ W_fc^T + b_fc   (M=16384, N=1024, K=1024)
    {
        dim3 grid(HIDDEN/128, MTOT/128);
        sgemm_bias<<<grid, 256>>>(dHout, W_fc, b_fc, nullptr, out, MTOT, HIDDEN, HIDDEN);
    }
}